// round 1
// baseline (speedup 1.0000x reference)
#include <cuda_runtime.h>

#define NCLS  3
#define NBOX  40
#define BATCH 16
#define A0 49152   // 128*128*3
#define A1 12288   // 64*64*3
#define A2 3072    // 32*32*3

// Scratch: per-anchor negative obj-loss (0 for non-negatives). ~4 MB.
__device__ float g_negloss[BATCH * (A0 + A1 + A2)];
__device__ int   g_npos[48];     // per (scale,batch)
__device__ int   g_nneg[48];
__device__ float g_obj, g_cls, g_loc;
__device__ int   g_tneg;

__global__ void init_kernel() {
    int t = threadIdx.x;
    if (t < 48) { g_npos[t] = 0; g_nneg[t] = 0; }
    if (t == 0) { g_obj = 0.f; g_cls = 0.f; g_loc = 0.f; g_tneg = 0; }
}

// One thread per spatial location (3 anchors each). Block handles one batch's chunk.
__global__ void main_kernel(const float* __restrict__ pred,
                            const float* __restrict__ anchors,
                            const float* __restrict__ boxes,
                            const int*   __restrict__ labels,
                            int H, int W, int sidx, int segOff)
{
    __shared__ float sbx[NBOX * 4];
    __shared__ int   slab[NBOX];
    __shared__ float redf[32];
    __shared__ int   redi[32];

    const int b = blockIdx.y;
    for (int i = threadIdx.x; i < NBOX * 4; i += blockDim.x) sbx[i]  = boxes[b * NBOX * 4 + i];
    for (int i = threadIdx.x; i < NBOX;     i += blockDim.x) slab[i] = labels[b * NBOX + i];
    __syncthreads();

    const int HW  = H * W;
    const int loc = blockIdx.x * blockDim.x + threadIdx.x;

    float l_obj = 0.f, l_cls = 0.f, l_loc = 0.f;
    int   l_pos = 0,   l_neg = 0;

    if (loc < HW) {
        const float* pb = pred + (size_t)b * 24 * HW + loc;
        #pragma unroll
        for (int j = 0; j < 3; j++) {
            const int a = loc * 3 + j;
            const float ax0 = anchors[4 * a + 0], ay0 = anchors[4 * a + 1];
            const float ax1 = anchors[4 * a + 2], ay1 = anchors[4 * a + 3];
            const float areaA = (ax1 - ax0) * (ay1 - ay0);

            float best = -1.f; int bi = 0;
            #pragma unroll 4
            for (int n = 0; n < NBOX; n++) {
                const float bx0 = sbx[4 * n + 0], by0 = sbx[4 * n + 1];
                const float bx1 = sbx[4 * n + 2], by1 = sbx[4 * n + 3];
                float iw = fminf(ax1, bx1) - fmaxf(ax0, bx0); iw = fmaxf(iw, 0.f);
                float ih = fminf(ay1, by1) - fmaxf(ay0, by0); ih = fmaxf(ih, 0.f);
                const float inter = iw * ih;
                const float areaB = (bx1 - bx0) * (by1 - by0);
                const float iou = inter / (areaA + areaB - inter + 1e-9f);
                if (iou > best) { best = iou; bi = n; }  // first-max, matches jnp.argmax
            }
            const bool pos = (best >= 0.5f);
            const bool neg = (best < 0.3f);

            float p[8];
            #pragma unroll
            for (int c = 0; c < 8; c++) p[c] = pb[(size_t)(j * 8 + c) * HW];

            const float obj = p[4];
            // stable softplus: max(x,0) + log1p(exp(-|x|))
            const float sp = fmaxf(obj, 0.f) + log1pf(expf(-fabsf(obj)));
            const float ol = sp - (pos ? obj : 0.f);

            g_negloss[segOff + b * (HW * 3) + a] = neg ? ol : 0.f;
            if (neg) l_neg++;

            if (pos) {
                l_pos++;
                l_obj += ol;
                // classification CE
                const float c0 = p[5], c1 = p[6], c2 = p[7];
                const float m  = fmaxf(c0, fmaxf(c1, c2));
                const float lse = m + logf(expf(c0 - m) + expf(c1 - m) + expf(c2 - m));
                int lab = slab[bi] - 1;
                lab = max(0, min(lab, NCLS - 1));
                const float tlog = (lab == 0) ? c0 : ((lab == 1) ? c1 : c2);
                l_cls += lse - tlog;
                // box regression (smooth L1 vs encoded target)
                const float bx0 = sbx[4 * bi + 0], by0 = sbx[4 * bi + 1];
                const float bx1 = sbx[4 * bi + 2], by1 = sbx[4 * bi + 3];
                const float aw = ax1 - ax0, ah = ay1 - ay0;
                const float acx = ax0 + 0.5f * aw, acy = ay0 + 0.5f * ah;
                const float gw = bx1 - bx0, gh = by1 - by0;
                const float gcx = bx0 + 0.5f * gw, gcy = by0 + 0.5f * gh;
                const float e0 = (gcx - acx) / aw;
                const float e1 = (gcy - acy) / ah;
                const float e2 = logf(gw / aw);
                const float e3 = logf(gh / ah);
                float d, ad, s = 0.f;
                d = p[0] - e0; ad = fabsf(d); s += (ad < 1.f) ? 0.5f * d * d : ad - 0.5f;
                d = p[1] - e1; ad = fabsf(d); s += (ad < 1.f) ? 0.5f * d * d : ad - 0.5f;
                d = p[2] - e2; ad = fabsf(d); s += (ad < 1.f) ? 0.5f * d * d : ad - 0.5f;
                d = p[3] - e3; ad = fabsf(d); s += (ad < 1.f) ? 0.5f * d * d : ad - 0.5f;
                l_loc += s;
            }
        }
    }

    // ---- block reductions + atomics ----
    const int lane = threadIdx.x & 31, wid = threadIdx.x >> 5, nw = blockDim.x >> 5;

    float fv[3] = { l_obj, l_cls, l_loc };
    float* ftgt[3] = { &g_obj, &g_cls, &g_loc };
    #pragma unroll
    for (int q = 0; q < 3; q++) {
        float v = fv[q];
        for (int o = 16; o; o >>= 1) v += __shfl_down_sync(0xffffffffu, v, o);
        if (lane == 0) redf[wid] = v;
        __syncthreads();
        if (threadIdx.x == 0) {
            float s = 0.f;
            for (int wq = 0; wq < nw; wq++) s += redf[wq];
            if (s != 0.f) atomicAdd(ftgt[q], s);
        }
        __syncthreads();
    }
    int iv[2] = { l_pos, l_neg };
    const int sb = sidx * BATCH + b;
    int* itgt[2] = { &g_npos[sb], &g_nneg[sb] };
    #pragma unroll
    for (int q = 0; q < 2; q++) {
        int v = iv[q];
        for (int o = 16; o; o >>= 1) v += __shfl_down_sync(0xffffffffu, v, o);
        if (lane == 0) redi[wid] = v;
        __syncthreads();
        if (threadIdx.x == 0) {
            int s = 0;
            for (int wq = 0; wq < nw; wq++) s += redi[wq];
            if (s != 0) atomicAdd(itgt[q], s);
        }
        __syncthreads();
    }
}

// One block per (scale,batch) segment: 4-pass MSB radix select -> sum of top-k.
__global__ void topk_kernel() {
    const int sb = blockIdx.x;
    const int s = sb / BATCH, b = sb % BATCH;
    const int As[3]   = { A0, A1, A2 };
    const int offs[3] = { 0, BATCH * A0, BATCH * (A0 + A1) };
    const int A = As[s];
    const float* seg = g_negloss + offs[s] + b * A;

    const int npos = g_npos[sb];
    const int nneg = g_nneg[sb];
    const int k = min(nneg, 3 * max(npos, 1));

    __shared__ unsigned int cnt[256];
    __shared__ float        bsum[256];
    __shared__ unsigned int sh_prefix;
    __shared__ int          sh_kk;
    __shared__ float        sh_sel;

    if (threadIdx.x == 0) { sh_prefix = 0u; sh_kk = k; sh_sel = 0.f; }
    __syncthreads();

    for (int pass = 0; pass < 4; pass++) {
        const int shift = 24 - 8 * pass;
        for (int i = threadIdx.x; i < 256; i += blockDim.x) { cnt[i] = 0u; bsum[i] = 0.f; }
        __syncthreads();

        const unsigned int maskHi = (pass == 0) ? 0u : (0xFFFFFFFFu << (32 - 8 * pass));
        const unsigned int pref = sh_prefix;
        if (sh_kk > 0) {
            for (int i = threadIdx.x; i < A; i += blockDim.x) {
                const float v = seg[i];
                if (v <= 0.f) continue;   // sentinel / impossible for real neg losses
                const unsigned int u = __float_as_uint(v);
                if ((u & maskHi) == pref) {
                    atomicAdd(&cnt[(u >> shift) & 0xFFu], 1u);
                    atomicAdd(&bsum[(u >> shift) & 0xFFu], v);
                }
            }
        }
        __syncthreads();

        if (threadIdx.x == 0 && sh_kk > 0) {
            const int kk = sh_kk;
            unsigned int cum = 0u;
            float ssum = 0.f;
            int j = 255;
            for (; j >= 0; j--) {
                if (cum + cnt[j] >= (unsigned int)kk) break;
                cum += cnt[j];
                ssum += bsum[j];
            }
            sh_sel += ssum;
            sh_kk = kk - (int)cum;
            sh_prefix = pref | ((unsigned int)j << shift);
        }
        __syncthreads();
    }

    if (threadIdx.x == 0) {
        if (k > 0) {
            const float total = sh_sel + (float)sh_kk * __uint_as_float(sh_prefix);
            atomicAdd(&g_obj, total);
            atomicAdd(&g_tneg, k);
        }
    }
}

__global__ void finalize_kernel(float* __restrict__ out) {
    int tp = 0;
    for (int i = 0; i < 48; i++) tp += g_npos[i];
    const float norm = fmaxf((float)tp, 1.f);
    const float lo = g_obj / norm;
    const float lc = g_cls / norm;
    const float ll = g_loc / norm;
    out[0] = lo;
    out[1] = lc;
    out[2] = ll;
    out[3] = lo + lc + 2.f * ll;
    out[4] = (float)tp;
    out[5] = (float)g_tneg;
}

extern "C" void kernel_launch(void* const* d_in, const int* in_sizes, int n_in,
                              void* d_out, int out_size)
{
    const float* pred0  = (const float*)d_in[0];
    const float* pred1  = (const float*)d_in[1];
    const float* pred2  = (const float*)d_in[2];
    const float* anc0   = (const float*)d_in[3];
    const float* anc1   = (const float*)d_in[4];
    const float* anc2   = (const float*)d_in[5];
    const float* boxes  = (const float*)d_in[6];
    const int*   labels = (const int*)d_in[7];
    float* out = (float*)d_out;

    init_kernel<<<1, 64>>>();

    dim3 g0((128 * 128 + 255) / 256, BATCH);
    main_kernel<<<g0, 256>>>(pred0, anc0, boxes, labels, 128, 128, 0, 0);
    dim3 g1((64 * 64 + 255) / 256, BATCH);
    main_kernel<<<g1, 256>>>(pred1, anc1, boxes, labels, 64, 64, 1, BATCH * A0);
    dim3 g2((32 * 32 + 255) / 256, BATCH);
    main_kernel<<<g2, 256>>>(pred2, anc2, boxes, labels, 32, 32, 2, BATCH * (A0 + A1));

    topk_kernel<<<48, 512>>>();
    finalize_kernel<<<1, 1>>>(out);
}

// round 15
// speedup vs baseline: 4.6682x; 4.6682x over previous
#include <cuda_runtime.h>

#define NCLS  3
#define NBOX  40
#define BATCH 16
#define A0 49152   // 128*128*3
#define A1 12288   // 64*64*3
#define A2 3072    // 32*32*3

// Scratch: per-anchor negative obj-loss (0 for non-negatives). ~4 MB.
__device__ float g_negloss[BATCH * (A0 + A1 + A2)];
__device__ int   g_npos[48];     // per (scale,batch)
__device__ int   g_nneg[48];
__device__ float g_obj, g_cls, g_loc;
__device__ int   g_tneg;

__global__ void init_kernel() {
    int t = threadIdx.x;
    if (t < 48) { g_npos[t] = 0; g_nneg[t] = 0; }
    if (t == 0) { g_obj = 0.f; g_cls = 0.f; g_loc = 0.f; g_tneg = 0; }
}

// Flat block mapping over (scale, batch, loc-chunk). 256 threads, 1 thread = 1 loc (3 anchors).
#define BLKS0 (16384/256)   // 64 per batch
#define BLKS1 (4096/256)    // 16 per batch
#define BLKS2 (1024/256)    // 4 per batch
#define NBLK0 (BLKS0*BATCH) // 1024
#define NBLK1 (BLKS1*BATCH) // 256
#define NBLK2 (BLKS2*BATCH) // 64

__global__ __launch_bounds__(256) void main_kernel(const float* __restrict__ pred0,
                                                   const float* __restrict__ pred1,
                                                   const float* __restrict__ pred2,
                                                   const float* __restrict__ boxes,
                                                   const int*   __restrict__ labels)
{
    __shared__ float4 sb4[NBOX];
    __shared__ float  sarea[NBOX];
    __shared__ int    slab[NBOX];
    __shared__ float  redf[8];
    __shared__ int    redi[8];

    // block -> (scale, batch, chunk)
    int bid = blockIdx.x;
    int s, b, chunk, H, W, segOff;
    float stride;
    const float* pred;
    if (bid < NBLK0)              { s = 0; b = bid / BLKS0; chunk = bid % BLKS0; H = 128; W = 128; stride = 8.f;  pred = pred0; segOff = 0; }
    else if (bid < NBLK0 + NBLK1) { int r = bid - NBLK0; s = 1; b = r / BLKS1; chunk = r % BLKS1; H = 64; W = 64; stride = 16.f; pred = pred1; segOff = BATCH * A0; }
    else                          { int r = bid - NBLK0 - NBLK1; s = 2; b = r / BLKS2; chunk = r % BLKS2; H = 32; W = 32; stride = 32.f; pred = pred2; segOff = BATCH * (A0 + A1); }

    for (int i = threadIdx.x; i < NBOX; i += blockDim.x) {
        float4 bb = ((const float4*)boxes)[b * NBOX + i];
        sb4[i] = bb;
        sarea[i] = (bb.z - bb.x) * (bb.w - bb.y);
        slab[i] = labels[b * NBOX + i];
    }
    __syncthreads();

    const int HW  = H * W;
    const int loc = chunk * blockDim.x + threadIdx.x;
    const int y = loc / W, x = loc % W;
    const float cx = ((float)x + 0.5f) * stride;
    const float cy = ((float)y + 0.5f) * stride;

    // 3 anchors: sizes (3,4,5)*stride, shared center
    float ax0[3], ay0[3], ax1[3], ay1[3], aA[3];
    #pragma unroll
    for (int j = 0; j < 3; j++) {
        const float sz = (float)(3 + j) * stride;
        const float h = 0.5f * sz;
        ax0[j] = cx - h; ay0[j] = cy - h; ax1[j] = cx + h; ay1[j] = cy + h;
        aA[j] = sz * sz;
    }

    float best[3] = { -1.f, -1.f, -1.f };
    int   bi[3]   = { 0, 0, 0 };
    #pragma unroll 4
    for (int n = 0; n < NBOX; n++) {
        const float4 bb = sb4[n];
        const float areaB = sarea[n];
        #pragma unroll
        for (int j = 0; j < 3; j++) {
            float iw = fminf(ax1[j], bb.z) - fmaxf(ax0[j], bb.x); iw = fmaxf(iw, 0.f);
            float ih = fminf(ay1[j], bb.w) - fmaxf(ay0[j], bb.y); ih = fmaxf(ih, 0.f);
            const float inter = iw * ih;
            const float iou = inter / (aA[j] + areaB - inter + 1e-9f);
            if (iou > best[j]) { best[j] = iou; bi[j] = n; }   // first-max == jnp.argmax
        }
    }

    float l_obj = 0.f, l_cls = 0.f, l_loc = 0.f;
    int   l_pos = 0,   l_neg = 0;
    const float* pb = pred + (size_t)b * 24 * HW + loc;

    #pragma unroll
    for (int j = 0; j < 3; j++) {
        const bool pos = (best[j] >= 0.5f);
        const bool neg = (best[j] < 0.3f);

        const float obj = pb[(size_t)(j * 8 + 4) * HW];
        const float sp  = fmaxf(obj, 0.f) + log1pf(expf(-fabsf(obj)));
        const float ol  = sp - (pos ? obj : 0.f);

        g_negloss[segOff + b * (HW * 3) + loc * 3 + j] = neg ? ol : 0.f;
        l_neg += neg ? 1 : 0;

        if (pos) {
            l_pos++;
            l_obj += ol;
            const float c0 = pb[(size_t)(j * 8 + 5) * HW];
            const float c1 = pb[(size_t)(j * 8 + 6) * HW];
            const float c2 = pb[(size_t)(j * 8 + 7) * HW];
            const float m  = fmaxf(c0, fmaxf(c1, c2));
            const float lse = m + logf(expf(c0 - m) + expf(c1 - m) + expf(c2 - m));
            const int n = bi[j];
            int lab = slab[n] - 1;
            lab = max(0, min(lab, NCLS - 1));
            const float tlog = (lab == 0) ? c0 : ((lab == 1) ? c1 : c2);
            l_cls += lse - tlog;

            const float4 bb = sb4[n];
            const float aw = ax1[j] - ax0[j], ah = ay1[j] - ay0[j];
            const float acx = ax0[j] + 0.5f * aw, acy = ay0[j] + 0.5f * ah;
            const float gw = bb.z - bb.x, gh = bb.w - bb.y;
            const float gcx = bb.x + 0.5f * gw, gcy = bb.y + 0.5f * gh;
            const float e0 = (gcx - acx) / aw;
            const float e1 = (gcy - acy) / ah;
            const float e2 = logf(gw / aw);
            const float e3 = logf(gh / ah);
            const float p0 = pb[(size_t)(j * 8 + 0) * HW];
            const float p1 = pb[(size_t)(j * 8 + 1) * HW];
            const float p2 = pb[(size_t)(j * 8 + 2) * HW];
            const float p3 = pb[(size_t)(j * 8 + 3) * HW];
            float d, ad, ss = 0.f;
            d = p0 - e0; ad = fabsf(d); ss += (ad < 1.f) ? 0.5f * d * d : ad - 0.5f;
            d = p1 - e1; ad = fabsf(d); ss += (ad < 1.f) ? 0.5f * d * d : ad - 0.5f;
            d = p2 - e2; ad = fabsf(d); ss += (ad < 1.f) ? 0.5f * d * d : ad - 0.5f;
            d = p3 - e3; ad = fabsf(d); ss += (ad < 1.f) ? 0.5f * d * d : ad - 0.5f;
            l_loc += ss;
        }
    }

    // ---- block reductions + atomics ----
    const int lane = threadIdx.x & 31, wid = threadIdx.x >> 5;

    float fv[3] = { l_obj, l_cls, l_loc };
    float* ftgt[3] = { &g_obj, &g_cls, &g_loc };
    #pragma unroll
    for (int q = 0; q < 3; q++) {
        float v = fv[q];
        for (int o = 16; o; o >>= 1) v += __shfl_down_sync(0xffffffffu, v, o);
        if (lane == 0) redf[wid] = v;
        __syncthreads();
        if (threadIdx.x == 0) {
            float sm = 0.f;
            #pragma unroll
            for (int wq = 0; wq < 8; wq++) sm += redf[wq];
            if (sm != 0.f) atomicAdd(ftgt[q], sm);
        }
        __syncthreads();
    }
    int iv[2] = { l_pos, l_neg };
    const int sb = s * BATCH + b;
    int* itgt[2] = { &g_npos[sb], &g_nneg[sb] };
    #pragma unroll
    for (int q = 0; q < 2; q++) {
        int v = iv[q];
        for (int o = 16; o; o >>= 1) v += __shfl_down_sync(0xffffffffu, v, o);
        if (lane == 0) redi[wid] = v;
        __syncthreads();
        if (threadIdx.x == 0) {
            int sm = 0;
            #pragma unroll
            for (int wq = 0; wq < 8; wq++) sm += redi[wq];
            if (sm != 0) atomicAdd(itgt[q], sm);
        }
        __syncthreads();
    }
}

// One block per (scale,batch): 4-pass count-only radix select (warp-aggregated
// atomics via match_any) -> exact 32-bit pivot -> one summation pass.
__global__ __launch_bounds__(512) void topk_kernel() {
    const int sb = blockIdx.x;
    const int s = sb / BATCH, b = sb % BATCH;
    const int As[3]   = { A0, A1, A2 };
    const int offs[3] = { 0, BATCH * A0, BATCH * (A0 + A1) };
    const int A = As[s];
    const float* __restrict__ seg = g_negloss + offs[s] + b * A;

    const int npos = g_npos[sb];
    const int nneg = g_nneg[sb];
    const int k = min(nneg, 3 * max(npos, 1));

    __shared__ unsigned int cnt[256];
    __shared__ unsigned int sh_prefix;
    __shared__ int          sh_kk;
    __shared__ float        redf[16];

    if (k <= 0) return;   // uniform across block (k computed from globals)

    if (threadIdx.x == 0) { sh_prefix = 0u; sh_kk = k; }
    const int lane = threadIdx.x & 31, wid = threadIdx.x >> 5;
    __syncthreads();

    #pragma unroll
    for (int pass = 0; pass < 4; pass++) {
        const int shift = 24 - 8 * pass;
        for (int i = threadIdx.x; i < 256; i += blockDim.x) cnt[i] = 0u;
        __syncthreads();

        const unsigned int maskHi = (pass == 0) ? 0u : (0xFFFFFFFFu << (32 - 8 * pass));
        const unsigned int pref = sh_prefix;
        for (int i = threadIdx.x; i < A; i += blockDim.x) {
            const float v = seg[i];
            const unsigned int u = __float_as_uint(v);
            const bool valid = (v > 0.f) && ((u & maskHi) == pref);
            const unsigned int key = valid ? ((u >> shift) & 0xFFu) : 0xFFFFFFFFu;
            const unsigned int grp = __match_any_sync(0xFFFFFFFFu, key);
            if (valid && lane == (__ffs(grp) - 1))
                atomicAdd(&cnt[key], (unsigned int)__popc(grp));
        }
        __syncthreads();

        if (threadIdx.x == 0) {
            const int kk = sh_kk;
            unsigned int cum = 0u;
            int j = 255;
            for (; j > 0; j--) {
                if (cum + cnt[j] >= (unsigned int)kk) break;
                cum += cnt[j];
            }
            sh_kk = kk - (int)cum;
            sh_prefix = pref | ((unsigned int)j << shift);
        }
        __syncthreads();
    }

    // Final pass: sum of all values strictly above the pivot; ties contribute
    // remaining_k * pivot_value (exact, since pivot is a full 32-bit pattern).
    const unsigned int pivot = sh_prefix;
    float acc = 0.f;
    for (int i = threadIdx.x; i < A; i += blockDim.x) {
        const float v = seg[i];
        if (v > 0.f && __float_as_uint(v) > pivot) acc += v;
    }
    for (int o = 16; o; o >>= 1) acc += __shfl_down_sync(0xffffffffu, acc, o);
    if (lane == 0) redf[wid] = acc;
    __syncthreads();
    if (threadIdx.x == 0) {
        float total = 0.f;
        #pragma unroll
        for (int wq = 0; wq < 16; wq++) total += redf[wq];
        total += (float)sh_kk * __uint_as_float(pivot);
        atomicAdd(&g_obj, total);
        atomicAdd(&g_tneg, k);
    }
}

__global__ void finalize_kernel(float* __restrict__ out) {
    int tp = 0;
    #pragma unroll
    for (int i = 0; i < 48; i++) tp += g_npos[i];
    const float norm = fmaxf((float)tp, 1.f);
    const float lo = g_obj / norm;
    const float lc = g_cls / norm;
    const float ll = g_loc / norm;
    out[0] = lo;
    out[1] = lc;
    out[2] = ll;
    out[3] = lo + lc + 2.f * ll;
    out[4] = (float)tp;
    out[5] = (float)g_tneg;
}

extern "C" void kernel_launch(void* const* d_in, const int* in_sizes, int n_in,
                              void* d_out, int out_size)
{
    const float* pred0  = (const float*)d_in[0];
    const float* pred1  = (const float*)d_in[1];
    const float* pred2  = (const float*)d_in[2];
    const float* boxes  = (const float*)d_in[6];
    const int*   labels = (const int*)d_in[7];
    float* out = (float*)d_out;

    init_kernel<<<1, 64>>>();
    main_kernel<<<NBLK0 + NBLK1 + NBLK2, 256>>>(pred0, pred1, pred2, boxes, labels);
    topk_kernel<<<48, 512>>>();
    finalize_kernel<<<1, 1>>>(out);
}